// round 2
// baseline (speedup 1.0000x reference)
#include <cuda_runtime.h>

// Problem constants
#define F_DIM 128
#define K_NEIGH 16
#define O_DIM 128
#define KD 256              // 2F concat width
#define TM 64               // nodes per block
#define THREADS 256
#define KC 64               // K chunk for W staging
#define WS_STRIDE 132       // padded (keeps 16B alignment, avoids write conflicts)
#define NEG_SLOPE 0.2f
#define LN_EPS 1e-5f

// dynamic smem layout (floats):
//   As   [TM][KD]          = 16384 floats
//   Ws   [KC][WS_STRIDE]   =  8448 floats
//   sAdj [TM][K_NEIGH] int =  1024 ints
//   sInv [TM]              =    64 floats
#define SMEM_FLOATS (TM*KD + KC*WS_STRIDE)
#define SMEM_BYTES  ((SMEM_FLOATS + TM*K_NEIGH + TM) * 4)

__global__ void __launch_bounds__(THREADS, 2)
gnn_fused_kernel(const float* __restrict__ X,
                 const int* __restrict__ adj,        // int32 (JAX x64 disabled)
                 const float* __restrict__ W,
                 const float* __restrict__ bias,
                 const float* __restrict__ gamma,
                 const float* __restrict__ beta,
                 float* __restrict__ out,
                 int N)
{
    extern __shared__ float smem[];
    float* As   = smem;                                   // [TM][KD]
    float* Ws   = As + TM * KD;                           // [KC][WS_STRIDE]
    int*   sAdj = (int*)(Ws + KC * WS_STRIDE);            // [TM][K_NEIGH]
    float* sInv = (float*)(sAdj + TM * K_NEIGH);          // [TM]

    const int tid  = threadIdx.x;
    const int lane = tid & 31;
    const int warp = tid >> 5;                            // 8 warps
    const int nodeBase = blockIdx.x * TM;

    // ---- Phase 1a: adjacency -> smem, x -> As[:, 0:128] ----
    for (int i = tid; i < TM * K_NEIGH; i += THREADS) {
        int r = i >> 4;
        int a = -1;
        if (nodeBase + r < N)
            a = adj[(long long)(nodeBase + r) * K_NEIGH + (i & (K_NEIGH - 1))];
        sAdj[i] = a;
    }
    for (int i = tid; i < TM * (F_DIM / 4); i += THREADS) {
        int r  = i / (F_DIM / 4);
        int c4 = i % (F_DIM / 4);
        float4 v = make_float4(0.f, 0.f, 0.f, 0.f);
        if (nodeBase + r < N)
            v = ((const float4*)X)[(long long)(nodeBase + r) * (F_DIM / 4) + c4];
        *(float4*)&As[r * KD + c4 * 4] = v;
    }
    __syncthreads();

    // ---- Phase 1b: per-node 1/denom ----
    if (tid < TM) {
        int cnt = 0;
        #pragma unroll
        for (int k = 0; k < K_NEIGH; k++)
            cnt += (sAdj[tid * K_NEIGH + k] >= 0) ? 1 : 0;
        sInv[tid] = 1.0f / (float)(cnt > 1 ? cnt : 1);
    }
    __syncthreads();

    // ---- Phase 1c: masked neighbor-mean gather -> As[:, 128:256] ----
    // warp handles 8 nodes; lane covers one float4 column (32 lanes * 4 = 128)
    #pragma unroll
    for (int i = 0; i < 8; i++) {
        int r = warp * 8 + i;
        float4 acc = make_float4(0.f, 0.f, 0.f, 0.f);
        #pragma unroll
        for (int k = 0; k < K_NEIGH; k++) {
            int j = sAdj[r * K_NEIGH + k];
            if (j >= 0) {
                float4 v = ((const float4*)X)[(long long)j * (F_DIM / 4) + lane];
                acc.x += v.x; acc.y += v.y; acc.z += v.z; acc.w += v.w;
            }
        }
        float inv = sInv[r];
        acc.x *= inv; acc.y *= inv; acc.z *= inv; acc.w *= inv;
        *(float4*)&As[r * KD + F_DIM + lane * 4] = acc;
    }

    // ---- Phase 2: GEMM  h = A @ W^T ----
    // thread computes 8 nodes (warp's rows) x 4 outputs (o = lane*4 .. +3)
    float acc[8][4] = {};

    #pragma unroll 1
    for (int kc = 0; kc < KD; kc += KC) {
        __syncthreads();   // covers As ready (first iter) + Ws reuse (later iters)
        // stage W chunk transposed: Ws[c][o] = W[o][kc+c]
        for (int i = tid; i < O_DIM * (KC / 4); i += THREADS) {
            int o  = i / (KC / 4);
            int c4 = i % (KC / 4);
            float4 v = ((const float4*)W)[((long long)o * KD + kc) / 4 + c4];
            Ws[(c4 * 4 + 0) * WS_STRIDE + o] = v.x;
            Ws[(c4 * 4 + 1) * WS_STRIDE + o] = v.y;
            Ws[(c4 * 4 + 2) * WS_STRIDE + o] = v.z;
            Ws[(c4 * 4 + 3) * WS_STRIDE + o] = v.w;
        }
        __syncthreads();

        #pragma unroll
        for (int k = 0; k < KC; k += 4) {
            float4 w0 = *(const float4*)&Ws[(k + 0) * WS_STRIDE + lane * 4];
            float4 w1 = *(const float4*)&Ws[(k + 1) * WS_STRIDE + lane * 4];
            float4 w2 = *(const float4*)&Ws[(k + 2) * WS_STRIDE + lane * 4];
            float4 w3 = *(const float4*)&Ws[(k + 3) * WS_STRIDE + lane * 4];
            #pragma unroll
            for (int i = 0; i < 8; i++) {
                float4 a = *(const float4*)&As[(warp * 8 + i) * KD + kc + k];
                acc[i][0] += a.x * w0.x; acc[i][1] += a.x * w0.y;
                acc[i][2] += a.x * w0.z; acc[i][3] += a.x * w0.w;
                acc[i][0] += a.y * w1.x; acc[i][1] += a.y * w1.y;
                acc[i][2] += a.y * w1.z; acc[i][3] += a.y * w1.w;
                acc[i][0] += a.z * w2.x; acc[i][1] += a.z * w2.y;
                acc[i][2] += a.z * w2.z; acc[i][3] += a.z * w2.w;
                acc[i][0] += a.w * w3.x; acc[i][1] += a.w * w3.y;
                acc[i][2] += a.w * w3.z; acc[i][3] += a.w * w3.w;
            }
        }
    }

    // ---- Phase 3: bias + LayerNorm (warp reduce over 32 lanes x 4 outs) + LeakyReLU ----
    float4 bb = *(const float4*)&bias [lane * 4];
    float4 gg = *(const float4*)&gamma[lane * 4];
    float4 be = *(const float4*)&beta [lane * 4];

    #pragma unroll
    for (int i = 0; i < 8; i++) {
        int r = warp * 8 + i;
        int node = nodeBase + r;
        if (node >= N) break;   // uniform within warp

        float h0 = acc[i][0] + bb.x;
        float h1 = acc[i][1] + bb.y;
        float h2 = acc[i][2] + bb.z;
        float h3 = acc[i][3] + bb.w;

        float s = h0 + h1 + h2 + h3;
        #pragma unroll
        for (int off = 16; off > 0; off >>= 1)
            s += __shfl_xor_sync(0xFFFFFFFFu, s, off);
        float mu = s * (1.0f / 128.0f);

        float d0 = h0 - mu, d1 = h1 - mu, d2 = h2 - mu, d3 = h3 - mu;
        float v = d0 * d0 + d1 * d1 + d2 * d2 + d3 * d3;
        #pragma unroll
        for (int off = 16; off > 0; off >>= 1)
            v += __shfl_xor_sync(0xFFFFFFFFu, v, off);
        float rstd = rsqrtf(v * (1.0f / 128.0f) + LN_EPS);

        float y0 = d0 * rstd * gg.x + be.x;
        float y1 = d1 * rstd * gg.y + be.y;
        float y2 = d2 * rstd * gg.z + be.z;
        float y3 = d3 * rstd * gg.w + be.w;
        y0 = (y0 >= 0.f) ? y0 : NEG_SLOPE * y0;
        y1 = (y1 >= 0.f) ? y1 : NEG_SLOPE * y1;
        y2 = (y2 >= 0.f) ? y2 : NEG_SLOPE * y2;
        y3 = (y3 >= 0.f) ? y3 : NEG_SLOPE * y3;

        float4 o4 = make_float4(y0, y1, y2, y3);
        *(float4*)&out[(long long)node * O_DIM + lane * 4] = o4;
    }
}

extern "C" void kernel_launch(void* const* d_in, const int* in_sizes, int n_in,
                              void* d_out, int out_size)
{
    const float* X     = (const float*)d_in[0];
    const int*   adj   = (const int*)d_in[1];      // int32, element count = N*16
    const float* W     = (const float*)d_in[2];
    const float* bias  = (const float*)d_in[3];
    const float* gamma = (const float*)d_in[4];
    const float* beta  = (const float*)d_in[5];
    float* out = (float*)d_out;

    int N = in_sizes[0] / F_DIM;

    cudaFuncSetAttribute(gnn_fused_kernel,
                         cudaFuncAttributeMaxDynamicSharedMemorySize, SMEM_BYTES);

    int grid = (N + TM - 1) / TM;
    gnn_fused_kernel<<<grid, THREADS, SMEM_BYTES>>>(X, adj, W, bias, gamma, beta, out, N);
}

// round 4
// speedup vs baseline: 1.2878x; 1.2878x over previous
#include <cuda_runtime.h>
#include <cuda_bf16.h>
#include <cstdint>

#define THREADS   256
#define TM        128
#define F_DIM     128
#define K_NEIGH   16
#define O_DIM     128
#define KD        256
#define NEG_SLOPE 0.2f
#define LN_EPS    1e-5f

// smem layout (bytes). A rows padded to 264 halves (528B), W rows to 136 halves (272B).
#define A_STRIDE_H 264
#define W_STRIDE_H 136
#define OFF_A_HI   0                         // 128*528 = 67584
#define OFF_A_LO   67584                     // 67584
#define OFF_W_HI   135168                    // 128*272 = 34816
#define OFF_W_LO   169984                    // 34816
#define OFF_ADJ    204800                    // 128*16*4 = 8192
#define OFF_INV    212992                    // 512
#define OFF_BIAS   213504                    // 512
#define OFF_GAM    214016                    // 512
#define OFF_BET    214528                    // 512
#define SMEM_BYTES 215040
#define OFF_H      0                         // h tile reuses A_HI: 128*129*4 = 66048
#define H_STRIDE   129

// pre-split W in device scratch (bf16 hi/lo, row-major [O][KD])
__device__ __nv_bfloat16 g_Whi[O_DIM * KD];
__device__ __nv_bfloat16 g_Wlo[O_DIM * KD];

__device__ __forceinline__ uint32_t smem_u32(const void* p) {
    uint32_t a;
    asm("{ .reg .u64 t; cvta.to.shared.u64 t, %1; cvt.u32.u64 %0, t; }" : "=r"(a) : "l"(p));
    return a;
}
__device__ __forceinline__ void ldsm4(uint32_t* r, uint32_t addr) {
    asm volatile("ldmatrix.sync.aligned.m8n8.x4.shared.b16 {%0,%1,%2,%3}, [%4];"
        : "=r"(r[0]), "=r"(r[1]), "=r"(r[2]), "=r"(r[3]) : "r"(addr));
}
__device__ __forceinline__ void mma_bf16(float* c, const uint32_t* a, const uint32_t* b) {
    asm volatile("mma.sync.aligned.m16n8k16.row.col.f32.bf16.bf16.f32 "
        "{%0,%1,%2,%3}, {%4,%5,%6,%7}, {%8,%9}, {%0,%1,%2,%3};"
        : "+f"(c[0]), "+f"(c[1]), "+f"(c[2]), "+f"(c[3])
        : "r"(a[0]), "r"(a[1]), "r"(a[2]), "r"(a[3]), "r"(b[0]), "r"(b[1]));
}
__device__ __forceinline__ uint32_t pk2(float a, float b) {
    __nv_bfloat162 t = __floats2bfloat162_rn(a, b);
    return *reinterpret_cast<uint32_t*>(&t);
}
__device__ __forceinline__ void split1(float v, float& h, float& l) {
    h = __bfloat162float(__float2bfloat16_rn(v));
    l = v - h;
}

// ---------- prep: split W into bf16 hi/lo ----------
__global__ void prep_w_kernel(const float* __restrict__ W) {
    int i = blockIdx.x * blockDim.x + threadIdx.x;
    if (i < O_DIM * KD) {
        float v = W[i];
        __nv_bfloat16 h = __float2bfloat16_rn(v);
        g_Whi[i] = h;
        g_Wlo[i] = __float2bfloat16_rn(v - __bfloat162float(h));
    }
}

// ---------- main fused kernel ----------
__global__ void __launch_bounds__(THREADS, 1)
gnn_mma_kernel(const float* __restrict__ X,
               const int* __restrict__ adj,
               const float* __restrict__ bias,
               const float* __restrict__ gamma,
               const float* __restrict__ beta,
               float* __restrict__ out,
               int N)
{
    extern __shared__ __align__(16) char sp[];
    const uint32_t sbase = smem_u32(sp);

    int*   sAdj = (int*)(sp + OFF_ADJ);
    float* sInv = (float*)(sp + OFF_INV);
    float* sB   = (float*)(sp + OFF_BIAS);
    float* sG   = (float*)(sp + OFF_GAM);
    float* sBe  = (float*)(sp + OFF_BET);
    float* hS   = (float*)(sp + OFF_H);

    const int tid  = threadIdx.x;
    const int lane = tid & 31;
    const int warp = tid >> 5;               // 8 warps
    const int warp_m = warp & 3;             // 4 in M (32 rows each)
    const int warp_n = warp >> 2;            // 2 in N (64 cols each)
    const int nodeBase = blockIdx.x * TM;
    const float4* X4 = (const float4*)X;

    if (tid < 128) { sB[tid] = bias[tid]; sG[tid] = gamma[tid]; sBe[tid] = beta[tid]; }

    // adjacency -> smem
    for (int i = tid; i < TM * K_NEIGH; i += THREADS) {
        int r = i >> 4;
        int a = -1;
        if (nodeBase + r < N) a = adj[(nodeBase + r) * K_NEIGH + (i & 15)];
        sAdj[i] = a;
    }
    // self features -> A cols [0,128), split hi/lo
    for (int i = tid; i < TM * 32; i += THREADS) {
        int r = i >> 5;
        int c = (i & 31) * 4;
        float4 v = make_float4(0.f, 0.f, 0.f, 0.f);
        if (nodeBase + r < N) v = X4[(nodeBase + r) * 32 + (i & 31)];
        float h0,h1,h2,h3,l0,l1,l2,l3;
        split1(v.x,h0,l0); split1(v.y,h1,l1); split1(v.z,h2,l2); split1(v.w,h3,l3);
        uint32_t off = (uint32_t)r * (A_STRIDE_H * 2) + (uint32_t)c * 2;
        *(uint2*)(sp + OFF_A_HI + off) = make_uint2(pk2(h0,h1), pk2(h2,h3));
        *(uint2*)(sp + OFF_A_LO + off) = make_uint2(pk2(l0,l1), pk2(l2,l3));
    }
    __syncthreads();

    if (tid < TM) {
        int cnt = 0;
        #pragma unroll
        for (int k = 0; k < K_NEIGH; k++) cnt += (sAdj[tid * K_NEIGH + k] >= 0);
        sInv[tid] = 1.0f / (float)(cnt > 1 ? cnt : 1);
    }
    __syncthreads();

    // gather: warp handles 16 nodes; lane covers one float4 column; mean -> A cols [128,256)
    #pragma unroll 1
    for (int ii = 0; ii < 16; ii++) {
        int r = warp * 16 + ii;
        float4 acc = make_float4(0.f, 0.f, 0.f, 0.f);
        #pragma unroll
        for (int k = 0; k < K_NEIGH; k++) {
            int j = sAdj[r * K_NEIGH + k];
            if (j >= 0) {
                float4 v = X4[j * 32 + lane];
                acc.x += v.x; acc.y += v.y; acc.z += v.z; acc.w += v.w;
            }
        }
        float inv = sInv[r];
        acc.x *= inv; acc.y *= inv; acc.z *= inv; acc.w *= inv;
        float h0,h1,h2,h3,l0,l1,l2,l3;
        split1(acc.x,h0,l0); split1(acc.y,h1,l1); split1(acc.z,h2,l2); split1(acc.w,h3,l3);
        uint32_t off = (uint32_t)r * (A_STRIDE_H * 2) + (uint32_t)(F_DIM + lane * 4) * 2;
        *(uint2*)(sp + OFF_A_HI + off) = make_uint2(pk2(h0,h1), pk2(h2,h3));
        *(uint2*)(sp + OFF_A_LO + off) = make_uint2(pk2(l0,l1), pk2(l2,l3));
    }

    // per-lane ldmatrix address components
    // A: lanes 0-15 -> rows m0-15 @k0; lanes 16-31 -> rows m0-15 @k8
    const uint32_t aRowByte = (uint32_t)(warp_m * 32 + (lane & 15)) * (A_STRIDE_H * 2)
                            + (uint32_t)(lane >> 4) * 16;
    // B: n = nbase + ((lane>>4)<<3) + (lane&7); k8 sel = (lane>>3)&1
    const uint32_t bRowByte = (uint32_t)(warp_n * 64 + ((lane >> 4) << 3) + (lane & 7)) * (W_STRIDE_H * 2)
                            + (uint32_t)((lane >> 3) & 1) * 16;

    float acc[2][8][4];
    #pragma unroll
    for (int mt = 0; mt < 2; mt++)
        #pragma unroll
        for (int nt = 0; nt < 8; nt++)
            #pragma unroll
            for (int j = 0; j < 4; j++) acc[mt][nt][j] = 0.f;

    __syncthreads();   // A tiles ready

    #pragma unroll 1
    for (int chunk = 0; chunk < 2; chunk++) {
        // stage W chunk (hi+lo) from pre-split global
        for (int idx = tid; idx < 128 * 16; idx += THREADS) {
            int o = idx >> 4;
            int c8 = (idx & 15) * 8;                     // halves
            int gi = o * KD + chunk * 128 + c8;
            uint32_t soff = (uint32_t)o * (W_STRIDE_H * 2) + (uint32_t)c8 * 2;
            *(uint4*)(sp + OFF_W_HI + soff) = *(const uint4*)(g_Whi + gi);
            *(uint4*)(sp + OFF_W_LO + soff) = *(const uint4*)(g_Wlo + gi);
        }
        __syncthreads();

        #pragma unroll 1
        for (int split = 0; split < 3; split++) {
            const uint32_t aBase = sbase + (split == 2 ? OFF_A_LO : OFF_A_HI)
                                 + aRowByte + (uint32_t)chunk * 256;  // chunk*128 halves
            const uint32_t bBase = sbase + (split == 1 ? OFF_W_LO : OFF_W_HI) + bRowByte;
            #pragma unroll
            for (int s = 0; s < 8; s++) {
                uint32_t a0[4], a1[4], b[16];
                ldsm4(a0, aBase + (uint32_t)s * 32);                              // mt=0
                ldsm4(a1, aBase + (uint32_t)s * 32 + 16 * (A_STRIDE_H * 2));      // mt=1
                #pragma unroll
                for (int q = 0; q < 4; q++)                                       // 2 n-tiles each
                    ldsm4(b + q * 4, bBase + (uint32_t)q * 16 * (W_STRIDE_H * 2)
                                           + (uint32_t)s * 32);
                #pragma unroll
                for (int nt = 0; nt < 8; nt++) {
                    mma_bf16(acc[0][nt], a0, b + nt * 2);
                    mma_bf16(acc[1][nt], a1, b + nt * 2);
                }
            }
        }
        __syncthreads();   // all ldmatrix of this chunk done before restage/reuse
    }

    // write h tile to smem (stride 129 floats, conflict-free column reads later)
    #pragma unroll
    for (int mt = 0; mt < 2; mt++) {
        int row = warp_m * 32 + mt * 16 + (lane >> 2);
        #pragma unroll
        for (int nt = 0; nt < 8; nt++) {
            int col = warp_n * 64 + nt * 8 + 2 * (lane & 3);
            hS[row * H_STRIDE + col]           = acc[mt][nt][0];
            hS[row * H_STRIDE + col + 1]       = acc[mt][nt][1];
            hS[(row + 8) * H_STRIDE + col]     = acc[mt][nt][2];
            hS[(row + 8) * H_STRIDE + col + 1] = acc[mt][nt][3];
        }
    }
    __syncthreads();

    // LayerNorm + LeakyReLU: one thread per row
    if (tid < TM) {
        int node = nodeBase + tid;
        const float* hrow = hS + tid * H_STRIDE;

        float v[128];
        float sum = 0.f;
        #pragma unroll
        for (int c = 0; c < 128; c++) { v[c] = hrow[c] + sB[c]; sum += v[c]; }
        float mu = sum * (1.0f / 128.0f);
        float var = 0.f;
        #pragma unroll
        for (int c = 0; c < 128; c++) { float t = v[c] - mu; var += t * t; }
        float rstd = rsqrtf(var * (1.0f / 128.0f) + LN_EPS);

        if (node < N) {
            float* orow = out + (size_t)node * O_DIM;
            #pragma unroll
            for (int c4 = 0; c4 < 32; c4++) {
                float y[4];
                #pragma unroll
                for (int j = 0; j < 4; j++) {
                    int c = c4 * 4 + j;
                    float t = (v[c] - mu) * rstd * sG[c] + sBe[c];
                    y[j] = (t >= 0.f) ? t : NEG_SLOPE * t;
                }
                *(float4*)(orow + c4 * 4) = make_float4(y[0], y[1], y[2], y[3]);
            }
        }
    }
}

extern "C" void kernel_launch(void* const* d_in, const int* in_sizes, int n_in,
                              void* d_out, int out_size)
{
    const float* X     = (const float*)d_in[0];
    const int*   adj   = (const int*)d_in[1];
    const float* W     = (const float*)d_in[2];
    const float* bias  = (const float*)d_in[3];
    const float* gamma = (const float*)d_in[4];
    const float* beta  = (const float*)d_in[5];
    float* out = (float*)d_out;

    int N = in_sizes[0] / F_DIM;

    prep_w_kernel<<<(O_DIM * KD + 255) / 256, 256>>>(W);

    cudaFuncSetAttribute(gnn_mma_kernel,
                         cudaFuncAttributeMaxDynamicSharedMemorySize, SMEM_BYTES);
    int grid = (N + TM - 1) / TM;
    gnn_mma_kernel<<<grid, THREADS, SMEM_BYTES>>>(X, adj, bias, gamma, beta, out, N);
}